// round 11
// baseline (speedup 1.0000x reference)
#include <cuda_runtime.h>
#include <cuda_bf16.h>
#include <cstdint>
#include <cstddef>

// Problem dims
#define HH   1024
#define K2H  2048
#define BB   8
#define SS   4096
#define LL   64
#define MTOT (BB * SS)               // 32768
#define CTX_ELEMS (BB * LL * HH)     // 524288

// Scratch (static device memory)
__device__ float g_scores[(size_t)BB * SS * LL];              // 8 MB
__device__ __nv_bfloat16 g_red_hi[(size_t)MTOT * HH];         // 64 MB
__device__ __nv_bfloat16 g_red_lo[(size_t)MTOT * HH];         // 64 MB
__device__ __nv_bfloat16 g_hid_hi[(size_t)LL * BB * HH];      // 1 MB
__device__ __nv_bfloat16 g_hid_lo[(size_t)LL * BB * HH];
__device__ __nv_bfloat16 g_wT_hi[(size_t)BB * LL * SS];       // 4 MB
__device__ __nv_bfloat16 g_wT_lo[(size_t)BB * LL * SS];

__device__ __forceinline__ uint32_t smem_u32(const void* p) {
    uint32_t a;
    asm("{ .reg .u64 t; cvta.to.shared.u64 t, %1; cvt.u32.u64 %0, t; }"
        : "=r"(a) : "l"(p));
    return a;
}
__device__ __forceinline__ uint32_t bf2_bits(__nv_bfloat162 h) {
    union { __nv_bfloat162 b; uint32_t u; } x; x.b = h; return x.u;
}
// ldmatrix x4 (non-transposed, b16)
__device__ __forceinline__ void ldmx4(uint32_t* r, uint32_t addr) {
    asm volatile("ldmatrix.sync.aligned.m8n8.x4.shared.b16 {%0,%1,%2,%3}, [%4];"
                 : "=r"(r[0]), "=r"(r[1]), "=r"(r[2]), "=r"(r[3]) : "r"(addr));
}
// ldmatrix x4 transposed
__device__ __forceinline__ void ldmx4t(uint32_t* r, uint32_t addr) {
    asm volatile("ldmatrix.sync.aligned.m8n8.x4.trans.shared.b16 {%0,%1,%2,%3}, [%4];"
                 : "=r"(r[0]), "=r"(r[1]), "=r"(r[2]), "=r"(r[3]) : "r"(addr));
}
// mma m16n8k16 row.col f32.bf16.bf16.f32, acc in-place
__device__ __forceinline__ void mma_bf16(float* d, const uint32_t* a,
                                         uint32_t b0, uint32_t b1) {
    asm volatile(
        "mma.sync.aligned.m16n8k16.row.col.f32.bf16.bf16.f32 "
        "{%0,%1,%2,%3}, {%4,%5,%6,%7}, {%8,%9}, {%0,%1,%2,%3};"
        : "+f"(d[0]), "+f"(d[1]), "+f"(d[2]), "+f"(d[3])
        : "r"(a[0]), "r"(a[1]), "r"(a[2]), "r"(a[3]), "r"(b0), "r"(b1));
}
// fp32 -> 2-plane bf16 split, store 4 elems (8 bytes/plane) to smem
__device__ __forceinline__ void split4_sts(uint32_t hi_addr, uint32_t lo_addr,
                                           float4 v) {
    __nv_bfloat162 h0 = __floats2bfloat162_rn(v.x, v.y);
    __nv_bfloat162 h1 = __floats2bfloat162_rn(v.z, v.w);
    float2 f0 = __bfloat1622float2(h0);
    float2 f1 = __bfloat1622float2(h1);
    __nv_bfloat162 l0 = __floats2bfloat162_rn(v.x - f0.x, v.y - f0.y);
    __nv_bfloat162 l1 = __floats2bfloat162_rn(v.z - f1.x, v.w - f1.y);
    asm volatile("st.shared.v2.b32 [%0], {%1, %2};"
                 :: "r"(hi_addr), "r"(bf2_bits(h0)), "r"(bf2_bits(h1)) : "memory");
    asm volatile("st.shared.v2.b32 [%0], {%1, %2};"
                 :: "r"(lo_addr), "r"(bf2_bits(l0)), "r"(bf2_bits(l1)) : "memory");
}
// split pair to global planes
__device__ __forceinline__ void split2_g(__nv_bfloat16* hi, __nv_bfloat16* lo,
                                         float a, float b) {
    __nv_bfloat162 h = __floats2bfloat162_rn(a, b);
    float2 f = __bfloat1622float2(h);
    __nv_bfloat162 l = __floats2bfloat162_rn(a - f.x, b - f.y);
    *reinterpret_cast<__nv_bfloat162*>(hi) = h;
    *reinterpret_cast<__nv_bfloat162*>(lo) = l;
}

// ============================================================
// Pre-split hidden [L,B,H] fp32 -> bf16 hi/lo planes
// ============================================================
__global__ void presplit_hidden(const float* __restrict__ hid) {
    int i4 = blockIdx.x * 256 + threadIdx.x;   // 0..131071
    float4 v = __ldg(reinterpret_cast<const float4*>(hid) + i4);
    split2_g(&g_hid_hi[(size_t)i4 * 4], &g_hid_lo[(size_t)i4 * 4], v.x, v.y);
    split2_g(&g_hid_hi[(size_t)i4 * 4 + 2], &g_hid_lo[(size_t)i4 * 4 + 2], v.z, v.w);
}

// ============================================================
// GEMM1 (HMMA split-bf16 x3, double-buffered):
//   reduced = Es @ W^T + bias  -> bf16 hi/lo planes
// CTA 128x128, K-chunk 32 fp32, 8 warps 4m x 2n (32x64 warp tile).
// dyn smem: A[2 stg][2 pl][128][40]h + B same = 80 KB.
// ============================================================
#define ROWH 40
#define G1_PLANE 10240u
#define G1_STAGE 20480u
#define G1_BOFF  40960u
#define G1_DYN   81920u

__global__ void __launch_bounds__(256, 1)
gemm1_mma(const float* __restrict__ A,    // [32768, 2048]
          const float* __restrict__ Wm,   // [1024, 2048]
          const float* __restrict__ bias) {
    extern __shared__ char dyn[];
    __shared__ float sBias[128];
    const uint32_t uA = smem_u32(dyn);
    const uint32_t uB = uA + G1_BOFF;

    const int tid  = threadIdx.x;
    const int bn   = blockIdx.x * 128;
    const int bm   = blockIdx.y * 128;
    const int warp = tid >> 5, lane = tid & 31;
    const int wm = warp & 3, wn = warp >> 2;

    if (tid < 32)
        *reinterpret_cast<float4*>(&sBias[tid * 4]) =
            *reinterpret_cast<const float4*>(&bias[bn + tid * 4]);

    const int lrow = tid >> 3;   // 0..31
    const int lc4  = tid & 7;

    float4 pa[4], pb[4];
#pragma unroll
    for (int u = 0; u < 4; u++) {
        pa[u] = __ldg(reinterpret_cast<const float4*>(
            &A[(size_t)(bm + lrow + u * 32) * K2H + lc4 * 4]));
        pb[u] = __ldg(reinterpret_cast<const float4*>(
            &Wm[(size_t)(bn + lrow + u * 32) * K2H + lc4 * 4]));
    }

    float acc[2][8][4];
#pragma unroll
    for (int mt = 0; mt < 2; mt++)
#pragma unroll
        for (int nt = 0; nt < 8; nt++)
#pragma unroll
            for (int e = 0; e < 4; e++) acc[mt][nt][e] = 0.f;

    const int g = lane >> 3, gl = lane & 7;
    const uint32_t aRowOff = (uint32_t)((wm * 32 + (g & 1) * 8 + gl) * 80);
    const uint32_t aKOff   = (uint32_t)((g >> 1) * 16);
    const uint32_t bRowOff = (uint32_t)((wn * 64 + (g >> 1) * 8 + gl) * 80);
    const uint32_t bKOff   = (uint32_t)((g & 1) * 16);

    const int PA[6] = {0, 0, 1, 1, 0, 0};
    const int PB[6] = {0, 0, 0, 0, 1, 1};
    const int KO[6] = {0, 32, 0, 32, 0, 32};   // bytes

    // prologue: store stage 0  (8 bytes per float4 per plane!)
#pragma unroll
    for (int u = 0; u < 4; u++) {
        uint32_t off = (uint32_t)((lrow + u * 32) * 80 + lc4 * 8);
        split4_sts(uA + off, uA + G1_PLANE + off, pa[u]);
        split4_sts(uB + off, uB + G1_PLANE + off, pb[u]);
    }
    __syncthreads();

    for (int it = 0; it < 64; it++) {
        const uint32_t so = (uint32_t)(it & 1) * G1_STAGE;
        const uint32_t sn = (uint32_t)((it + 1) & 1) * G1_STAGE;
        if (it < 63) {
            const int kt = (it + 1) * 32;
#pragma unroll
            for (int u = 0; u < 4; u++) {
                pa[u] = __ldg(reinterpret_cast<const float4*>(
                    &A[(size_t)(bm + lrow + u * 32) * K2H + kt + lc4 * 4]));
                pb[u] = __ldg(reinterpret_cast<const float4*>(
                    &Wm[(size_t)(bn + lrow + u * 32) * K2H + kt + lc4 * 4]));
            }
        }
#pragma unroll
        for (int s = 0; s < 6; s++) {
            const uint32_t baseA = uA + so + (uint32_t)PA[s] * G1_PLANE + (uint32_t)KO[s];
            const uint32_t baseB = uB + so + (uint32_t)PB[s] * G1_PLANE + (uint32_t)KO[s];
            uint32_t af[2][4];
#pragma unroll
            for (int mt = 0; mt < 2; mt++)
                ldmx4(af[mt], baseA + aRowOff + (uint32_t)(mt * 1280) + aKOff);
            uint32_t bf[4][4];
#pragma unroll
            for (int p = 0; p < 4; p++)
                ldmx4(bf[p], baseB + bRowOff + (uint32_t)(p * 1280) + bKOff);
#pragma unroll
            for (int mt = 0; mt < 2; mt++)
#pragma unroll
                for (int p = 0; p < 4; p++) {
                    mma_bf16(acc[mt][2 * p + 0], af[mt], bf[p][0], bf[p][1]);
                    mma_bf16(acc[mt][2 * p + 1], af[mt], bf[p][2], bf[p][3]);
                }
        }
        if (it < 63) {
#pragma unroll
            for (int u = 0; u < 4; u++) {
                uint32_t off = (uint32_t)((lrow + u * 32) * 80 + lc4 * 8);
                split4_sts(uA + sn + off, uA + sn + G1_PLANE + off, pa[u]);
                split4_sts(uB + sn + off, uB + sn + G1_PLANE + off, pb[u]);
            }
        }
        __syncthreads();
    }

    // epilogue: add bias, split to bf16 hi/lo planes
    const int mrow0 = bm + wm * 32 + (lane >> 2);
    const int ncol0 = wn * 64 + 2 * (lane & 3);
#pragma unroll
    for (int mt = 0; mt < 2; mt++)
#pragma unroll
        for (int nt = 0; nt < 8; nt++) {
            const int n = ncol0 + nt * 8;
            const float b0 = sBias[n], b1 = sBias[n + 1];
            const size_t r0 = (size_t)(mrow0 + mt * 16) * HH + bn + n;
            const size_t r1 = r0 + (size_t)8 * HH;
            split2_g(&g_red_hi[r0], &g_red_lo[r0],
                     acc[mt][nt][0] + b0, acc[mt][nt][1] + b1);
            split2_g(&g_red_hi[r1], &g_red_lo[r1],
                     acc[mt][nt][2] + b0, acc[mt][nt][3] + b1);
        }
}

// ============================================================
// GEMM2 (HMMA x3): scores[b][s][l] = sum_h red[s][h]*hid[l][h]
// CTA 128(s) x 64(l), K=1024, chunk 32 halves. 8 warps 4m x 2n.
// ============================================================
__global__ void __launch_bounds__(256, 2)
gemm2_mma() {
    __shared__ __nv_bfloat16 s2A[2][128][ROWH];   // [plane][s][k]
    __shared__ __nv_bfloat16 s2B[2][64][ROWH];    // [plane][l][k]

    const int tid = threadIdx.x;
    const int b = blockIdx.y, bs = blockIdx.x * 128;
    const int warp = tid >> 5, lane = tid & 31;
    const int wm = warp & 3, wn = warp >> 2;

    const __nv_bfloat16* Ah = g_red_hi + (size_t)(b * SS + bs) * HH;
    const __nv_bfloat16* Al = g_red_lo + (size_t)(b * SS + bs) * HH;
    const __nv_bfloat16* Bh = g_hid_hi + (size_t)b * HH;
    const __nv_bfloat16* Bl = g_hid_lo + (size_t)b * HH;

    const int ar0 = (tid * 2) >> 2, ac0 = (tid * 2) & 3;
    const int ar1 = (tid * 2 + 1) >> 2, ac1 = (tid * 2 + 1) & 3;
    const int brow = tid >> 2, bc = tid & 3;

    uint4 qa[2][2], qb[2];
    qa[0][0] = *reinterpret_cast<const uint4*>(&Ah[(size_t)ar0 * HH + ac0 * 8]);
    qa[0][1] = *reinterpret_cast<const uint4*>(&Ah[(size_t)ar1 * HH + ac1 * 8]);
    qa[1][0] = *reinterpret_cast<const uint4*>(&Al[(size_t)ar0 * HH + ac0 * 8]);
    qa[1][1] = *reinterpret_cast<const uint4*>(&Al[(size_t)ar1 * HH + ac1 * 8]);
    qb[0] = *reinterpret_cast<const uint4*>(&Bh[(size_t)brow * (BB * HH) + bc * 8]);
    qb[1] = *reinterpret_cast<const uint4*>(&Bl[(size_t)brow * (BB * HH) + bc * 8]);

    float acc[2][4][4];
#pragma unroll
    for (int mt = 0; mt < 2; mt++)
#pragma unroll
        for (int nt = 0; nt < 4; nt++)
#pragma unroll
            for (int e = 0; e < 4; e++) acc[mt][nt][e] = 0.f;

    const int g = lane >> 3, gl = lane & 7;
    const uint32_t uA = smem_u32(s2A), uB = smem_u32(s2B);
    const uint32_t aRowOff = (uint32_t)((wm * 32 + (g & 1) * 8 + gl) * 80);
    const uint32_t aKOff   = (uint32_t)((g >> 1) * 16);
    const uint32_t bRowOff = (uint32_t)((wn * 32 + (g >> 1) * 8 + gl) * 80);
    const uint32_t bKOff   = (uint32_t)((g & 1) * 16);

    const int PA[6] = {0, 0, 1, 1, 0, 0};
    const int PB[6] = {0, 0, 0, 0, 1, 1};
    const int KO[6] = {0, 32, 0, 32, 0, 32};

    for (int it = 0; it < 32; it++) {
        __syncthreads();
        *reinterpret_cast<uint4*>(&s2A[0][ar0][ac0 * 8]) = qa[0][0];
        *reinterpret_cast<uint4*>(&s2A[0][ar1][ac1 * 8]) = qa[0][1];
        *reinterpret_cast<uint4*>(&s2A[1][ar0][ac0 * 8]) = qa[1][0];
        *reinterpret_cast<uint4*>(&s2A[1][ar1][ac1 * 8]) = qa[1][1];
        *reinterpret_cast<uint4*>(&s2B[0][brow][bc * 8]) = qb[0];
        *reinterpret_cast<uint4*>(&s2B[1][brow][bc * 8]) = qb[1];
        __syncthreads();
        if (it < 31) {
            const int ht = (it + 1) * 32;
            qa[0][0] = *reinterpret_cast<const uint4*>(&Ah[(size_t)ar0 * HH + ht + ac0 * 8]);
            qa[0][1] = *reinterpret_cast<const uint4*>(&Ah[(size_t)ar1 * HH + ht + ac1 * 8]);
            qa[1][0] = *reinterpret_cast<const uint4*>(&Al[(size_t)ar0 * HH + ht + ac0 * 8]);
            qa[1][1] = *reinterpret_cast<const uint4*>(&Al[(size_t)ar1 * HH + ht + ac1 * 8]);
            qb[0] = *reinterpret_cast<const uint4*>(&Bh[(size_t)brow * (BB * HH) + ht + bc * 8]);
            qb[1] = *reinterpret_cast<const uint4*>(&Bl[(size_t)brow * (BB * HH) + ht + bc * 8]);
        }
#pragma unroll
        for (int s = 0; s < 6; s++) {
            const uint32_t baseA = uA + (uint32_t)PA[s] * 10240u + (uint32_t)KO[s];
            const uint32_t baseB = uB + (uint32_t)PB[s] * 5120u + (uint32_t)KO[s];
            uint32_t af[2][4];
#pragma unroll
            for (int mt = 0; mt < 2; mt++)
                ldmx4(af[mt], baseA + aRowOff + (uint32_t)(mt * 1280) + aKOff);
            uint32_t bf[2][4];
#pragma unroll
            for (int p = 0; p < 2; p++)
                ldmx4(bf[p], baseB + bRowOff + (uint32_t)(p * 1280) + bKOff);
#pragma unroll
            for (int mt = 0; mt < 2; mt++)
#pragma unroll
                for (int p = 0; p < 2; p++) {
                    mma_bf16(acc[mt][2 * p + 0], af[mt], bf[p][0], bf[p][1]);
                    mma_bf16(acc[mt][2 * p + 1], af[mt], bf[p][2], bf[p][3]);
                }
        }
    }

    const int mrow0 = bs + wm * 32 + (lane >> 2);
    const int ncol0 = wn * 32 + 2 * (lane & 3);
#pragma unroll
    for (int mt = 0; mt < 2; mt++)
#pragma unroll
        for (int nt = 0; nt < 4; nt++) {
            const int n = ncol0 + nt * 8;
            *reinterpret_cast<float2*>(
                &g_scores[((size_t)b * SS + mrow0 + mt * 16) * LL + n]) =
                make_float2(acc[mt][nt][0], acc[mt][nt][1]);
            *reinterpret_cast<float2*>(
                &g_scores[((size_t)b * SS + mrow0 + mt * 16 + 8) * LL + n]) =
                make_float2(acc[mt][nt][2], acc[mt][nt][3]);
        }
}

// ============================================================
// Softmax over s for each (b,l): fp32 weights out + wT bf16 planes
// ============================================================
__global__ void softmax_kernel(float* __restrict__ wout) {
    const int b = blockIdx.x >> 6;
    const int l = blockIdx.x & 63;
    const int tid = threadIdx.x;
    const float* col = g_scores + (size_t)b * SS * LL + l;

    float v[16];
    float m = -3.4e38f;
#pragma unroll
    for (int i = 0; i < 16; i++) {
        v[i] = col[(size_t)(i * 256 + tid) * LL];
        m = fmaxf(m, v[i]);
    }
#pragma unroll
    for (int o = 16; o; o >>= 1) m = fmaxf(m, __shfl_xor_sync(0xffffffffu, m, o));

    __shared__ float red[8];
    __shared__ float bcast;
    if ((tid & 31) == 0) red[tid >> 5] = m;
    __syncthreads();
    if (tid == 0) {
        float mm = red[0];
#pragma unroll
        for (int i = 1; i < 8; i++) mm = fmaxf(mm, red[i]);
        bcast = mm;
    }
    __syncthreads();
    m = bcast;

    float s = 0.f;
#pragma unroll
    for (int i = 0; i < 16; i++) { v[i] = expf(v[i] - m); s += v[i]; }
#pragma unroll
    for (int o = 16; o; o >>= 1) s += __shfl_xor_sync(0xffffffffu, s, o);
    if ((tid & 31) == 0) red[tid >> 5] = s;
    __syncthreads();
    if (tid == 0) {
        float ss = 0.f;
#pragma unroll
        for (int i = 0; i < 8; i++) ss += red[i];
        bcast = ss;
    }
    __syncthreads();
    const float inv = 1.0f / bcast;

    float* out = wout + (size_t)b * SS * LL + l;
    __nv_bfloat16* wth = g_wT_hi + ((size_t)b * LL + l) * SS;
    __nv_bfloat16* wtl = g_wT_lo + ((size_t)b * LL + l) * SS;
#pragma unroll
    for (int i = 0; i < 16; i++) {
        const int si = i * 256 + tid;
        const float w = v[i] * inv;
        out[(size_t)si * LL] = w;
        __nv_bfloat16 h = __float2bfloat16(w);
        wth[si] = h;
        wtl[si] = __float2bfloat16(w - __bfloat162float(h));
    }
}

// ============================================================
// GEMM3 (HMMA x3): ctx[b][l][h] = sum_s wT[b][l][s]*red[s][h]
// CTA 64(l) x 64(h), K=4096, chunk 32. 8 warps 2m x 4n.
// A = wT planes (k-major, non-trans); B = red planes via trans-ldmatrix.
// ============================================================
__global__ void __launch_bounds__(256, 1)
gemm3_mma(float* __restrict__ ctx) {
    __shared__ __nv_bfloat16 sW[2][2][64][ROWH];   // [stg][pl][l][k=s] 20480B
    __shared__ __nv_bfloat16 sR[2][2][32][72];     // [stg][pl][s][h]   18432B

    const int tid = threadIdx.x;
    const int b = blockIdx.y, h0 = blockIdx.x * 64;
    const int warp = tid >> 5, lane = tid & 31;
    const int wm = warp & 1, wn = warp >> 1;

    const __nv_bfloat16* Wh = g_wT_hi + (size_t)b * LL * SS;
    const __nv_bfloat16* Wl = g_wT_lo + (size_t)b * LL * SS;
    const __nv_bfloat16* Rh = g_red_hi + (size_t)b * SS * HH + h0;
    const __nv_bfloat16* Rl = g_red_lo + (size_t)b * SS * HH + h0;

    const int wrow = tid >> 2, wc = tid & 3;   // A staging: 64 rows x 4 f4
    const int srow = tid >> 3, hc = tid & 7;   // B staging: 32 rows x 8 f4

    uint4 qw[2], qr[2];
    qw[0] = *reinterpret_cast<const uint4*>(&Wh[(size_t)wrow * SS + wc * 8]);
    qw[1] = *reinterpret_cast<const uint4*>(&Wl[(size_t)wrow * SS + wc * 8]);
    qr[0] = *reinterpret_cast<const uint4*>(&Rh[(size_t)srow * HH + hc * 8]);
    qr[1] = *reinterpret_cast<const uint4*>(&Rl[(size_t)srow * HH + hc * 8]);

    *reinterpret_cast<uint4*>(&sW[0][0][wrow][wc * 8]) = qw[0];
    *reinterpret_cast<uint4*>(&sW[0][1][wrow][wc * 8]) = qw[1];
    *reinterpret_cast<uint4*>(&sR[0][0][srow][hc * 8]) = qr[0];
    *reinterpret_cast<uint4*>(&sR[0][1][srow][hc * 8]) = qr[1];
    __syncthreads();

    float acc[2][2][4];
#pragma unroll
    for (int mt = 0; mt < 2; mt++)
#pragma unroll
        for (int nt = 0; nt < 2; nt++)
#pragma unroll
            for (int e = 0; e < 4; e++) acc[mt][nt][e] = 0.f;

    const int g = lane >> 3, gl = lane & 7;
    const uint32_t uW = smem_u32(sW), uR = smem_u32(sR);
    const uint32_t aRowOff = (uint32_t)((wm * 32 + (g & 1) * 8 + gl) * 80);
    const uint32_t aKOff   = (uint32_t)((g >> 1) * 16);
    // trans B addressing: lane%16 -> k row (144B stride), lane/16 -> 16B n-chunk
    const uint32_t bOff = (uint32_t)((lane & 15) * 144 + (wn * 16 + (lane >> 4) * 8) * 2);

    const int PA[6]  = {0, 0, 1, 1, 0, 0};
    const int PB[6]  = {0, 0, 0, 0, 1, 1};
    const int KOA[6] = {0, 32, 0, 32, 0, 32};          // A: bytes (16 halves)
    const int KOR[6] = {0, 2304, 0, 2304, 0, 2304};    // B: 16 rows x 144B

    for (int it = 0; it < 128; it++) {
        const uint32_t sow = (uint32_t)(it & 1) * 10240u;
        const uint32_t sor = (uint32_t)(it & 1) * 9216u;
        const uint32_t snw = (uint32_t)((it + 1) & 1) * 10240u;
        const uint32_t snr = (uint32_t)((it + 1) & 1) * 9216u;
        if (it < 127) {
            const int st = (it + 1) * 32;
            qw[0] = *reinterpret_cast<const uint4*>(&Wh[(size_t)wrow * SS + st + wc * 8]);
            qw[1] = *reinterpret_cast<const uint4*>(&Wl[(size_t)wrow * SS + st + wc * 8]);
            qr[0] = *reinterpret_cast<const uint4*>(&Rh[(size_t)(st + srow) * HH + hc * 8]);
            qr[1] = *reinterpret_cast<const uint4*>(&Rl[(size_t)(st + srow) * HH + hc * 8]);
        }
#pragma unroll
        for (int s = 0; s < 6; s++) {
            const uint32_t baseW = uW + sow + (uint32_t)PA[s] * 5120u + (uint32_t)KOA[s];
            const uint32_t baseR = uR + sor + (uint32_t)PB[s] * 4608u + (uint32_t)KOR[s];
            uint32_t af[2][4];
#pragma unroll
            for (int mt = 0; mt < 2; mt++)
                ldmx4(af[mt], baseW + aRowOff + (uint32_t)(mt * 1280) + aKOff);
            uint32_t bfr[4];
            ldmx4t(bfr, baseR + bOff);
#pragma unroll
            for (int mt = 0; mt < 2; mt++) {
                mma_bf16(acc[mt][0], af[mt], bfr[0], bfr[1]);
                mma_bf16(acc[mt][1], af[mt], bfr[2], bfr[3]);
            }
        }
        if (it < 127) {
            *reinterpret_cast<uint4*>(
                reinterpret_cast<char*>(sW) + snw + 0 * 5120u + (size_t)wrow * 80 + wc * 16) = qw[0];
            *reinterpret_cast<uint4*>(
                reinterpret_cast<char*>(sW) + snw + 1 * 5120u + (size_t)wrow * 80 + wc * 16) = qw[1];
            *reinterpret_cast<uint4*>(
                reinterpret_cast<char*>(sR) + snr + 0 * 4608u + (size_t)srow * 144 + hc * 16) = qr[0];
            *reinterpret_cast<uint4*>(
                reinterpret_cast<char*>(sR) + snr + 1 * 4608u + (size_t)srow * 144 + hc * 16) = qr[1];
        }
        __syncthreads();
    }

    // epilogue: direct fp32 ctx write (full K covered per CTA)
#pragma unroll
    for (int mt = 0; mt < 2; mt++)
#pragma unroll
        for (int nt = 0; nt < 2; nt++) {
            const int l = wm * 32 + mt * 16 + (lane >> 2);
            const int h = h0 + wn * 16 + nt * 8 + 2 * (lane & 3);
            *reinterpret_cast<float2*>(&ctx[((size_t)b * LL + l) * HH + h]) =
                make_float2(acc[mt][nt][0], acc[mt][nt][1]);
            *reinterpret_cast<float2*>(&ctx[((size_t)b * LL + l + 8) * HH + h]) =
                make_float2(acc[mt][nt][2], acc[mt][nt][3]);
        }
}

extern "C" void kernel_launch(void* const* d_in, const int* in_sizes, int n_in,
                              void* d_out, int out_size) {
    const float* hidden = (const float*)d_in[0];  // [L, B, H]
    const float* enc    = (const float*)d_in[1];  // [B, S, 2H]
    const float* Wm     = (const float*)d_in[2];  // [H, 2H]
    const float* bias   = (const float*)d_in[3];  // [H]

    float* ctx = (float*)d_out;                   // context [B, L, H]
    float* wts = (float*)d_out + CTX_ELEMS;       // weights [B, S, L]

    cudaFuncSetAttribute(gemm1_mma, cudaFuncAttributeMaxDynamicSharedMemorySize,
                         G1_DYN);
    presplit_hidden<<<512, 256>>>(hidden);
    gemm1_mma<<<dim3(HH / 128, MTOT / 128), 256, G1_DYN>>>(enc, Wm, bias);
    gemm2_mma<<<dim3(SS / 128, BB), 256>>>();
    softmax_kernel<<<BB * LL, 256>>>(wts);
    gemm3_mma<<<dim3(HH / 64, BB), 256>>>(ctx);
}

// round 12
// speedup vs baseline: 1.0025x; 1.0025x over previous
#include <cuda_runtime.h>
#include <cuda_bf16.h>
#include <cstdint>
#include <cstddef>

// Problem dims
#define HH   1024
#define K2H  2048
#define BB   8
#define SS   4096
#define LL   64
#define MTOT (BB * SS)               // 32768
#define CTX_ELEMS (BB * LL * HH)     // 524288

// Scratch (static device memory)
__device__ float g_scores[(size_t)BB * SS * LL];              // 8 MB
__device__ __nv_bfloat16 g_red_hi[(size_t)MTOT * HH];         // 64 MB
__device__ __nv_bfloat16 g_red_lo[(size_t)MTOT * HH];         // 64 MB
__device__ __nv_bfloat16 g_hid_hi[(size_t)LL * BB * HH];      // 1 MB
__device__ __nv_bfloat16 g_hid_lo[(size_t)LL * BB * HH];
__device__ __nv_bfloat16 g_wT_hi[(size_t)BB * LL * SS];       // 4 MB
__device__ __nv_bfloat16 g_wT_lo[(size_t)BB * LL * SS];

__device__ __forceinline__ uint32_t smem_u32(const void* p) {
    uint32_t a;
    asm("{ .reg .u64 t; cvta.to.shared.u64 t, %1; cvt.u32.u64 %0, t; }"
        : "=r"(a) : "l"(p));
    return a;
}
__device__ __forceinline__ uint32_t bf2_bits(__nv_bfloat162 h) {
    union { __nv_bfloat162 b; uint32_t u; } x; x.b = h; return x.u;
}
// ldmatrix x4 (non-transposed, b16)
__device__ __forceinline__ void ldmx4(uint32_t* r, uint32_t addr) {
    asm volatile("ldmatrix.sync.aligned.m8n8.x4.shared.b16 {%0,%1,%2,%3}, [%4];"
                 : "=r"(r[0]), "=r"(r[1]), "=r"(r[2]), "=r"(r[3]) : "r"(addr));
}
// ldmatrix x4 transposed
__device__ __forceinline__ void ldmx4t(uint32_t* r, uint32_t addr) {
    asm volatile("ldmatrix.sync.aligned.m8n8.x4.trans.shared.b16 {%0,%1,%2,%3}, [%4];"
                 : "=r"(r[0]), "=r"(r[1]), "=r"(r[2]), "=r"(r[3]) : "r"(addr));
}
// mma m16n8k16 row.col f32.bf16.bf16.f32, acc in-place
__device__ __forceinline__ void mma_bf16(float* d, const uint32_t* a,
                                         uint32_t b0, uint32_t b1) {
    asm volatile(
        "mma.sync.aligned.m16n8k16.row.col.f32.bf16.bf16.f32 "
        "{%0,%1,%2,%3}, {%4,%5,%6,%7}, {%8,%9}, {%0,%1,%2,%3};"
        : "+f"(d[0]), "+f"(d[1]), "+f"(d[2]), "+f"(d[3])
        : "r"(a[0]), "r"(a[1]), "r"(a[2]), "r"(a[3]), "r"(b0), "r"(b1));
}
// fp32 -> 2-plane bf16 split, store 4 elems (8 bytes/plane) to smem
__device__ __forceinline__ void split4_sts(uint32_t hi_addr, uint32_t lo_addr,
                                           float4 v) {
    __nv_bfloat162 h0 = __floats2bfloat162_rn(v.x, v.y);
    __nv_bfloat162 h1 = __floats2bfloat162_rn(v.z, v.w);
    float2 f0 = __bfloat1622float2(h0);
    float2 f1 = __bfloat1622float2(h1);
    __nv_bfloat162 l0 = __floats2bfloat162_rn(v.x - f0.x, v.y - f0.y);
    __nv_bfloat162 l1 = __floats2bfloat162_rn(v.z - f1.x, v.w - f1.y);
    asm volatile("st.shared.v2.b32 [%0], {%1, %2};"
                 :: "r"(hi_addr), "r"(bf2_bits(h0)), "r"(bf2_bits(h1)) : "memory");
    asm volatile("st.shared.v2.b32 [%0], {%1, %2};"
                 :: "r"(lo_addr), "r"(bf2_bits(l0)), "r"(bf2_bits(l1)) : "memory");
}
// split pair to global planes
__device__ __forceinline__ void split2_g(__nv_bfloat16* hi, __nv_bfloat16* lo,
                                         float a, float b) {
    __nv_bfloat162 h = __floats2bfloat162_rn(a, b);
    float2 f = __bfloat1622float2(h);
    __nv_bfloat162 l = __floats2bfloat162_rn(a - f.x, b - f.y);
    *reinterpret_cast<__nv_bfloat162*>(hi) = h;
    *reinterpret_cast<__nv_bfloat162*>(lo) = l;
}

// ============================================================
// Pre-split hidden [L,B,H] fp32 -> bf16 hi/lo planes
// ============================================================
__global__ void presplit_hidden(const float* __restrict__ hid) {
    int i4 = blockIdx.x * 256 + threadIdx.x;   // 0..131071
    float4 v = __ldg(reinterpret_cast<const float4*>(hid) + i4);
    split2_g(&g_hid_hi[(size_t)i4 * 4], &g_hid_lo[(size_t)i4 * 4], v.x, v.y);
    split2_g(&g_hid_hi[(size_t)i4 * 4 + 2], &g_hid_lo[(size_t)i4 * 4 + 2], v.z, v.w);
}

// ============================================================
// GEMM1 (HMMA split-bf16 x3, double-buffered):
//   reduced = Es @ W^T + bias  -> bf16 hi/lo planes
// CTA 128x128, K-chunk 32 fp32, 8 warps 4m x 2n (32x64 warp tile).
// dyn smem: A[2 stg][2 pl][128][40]h + B same = 80 KB.
// ============================================================
#define ROWH 40
#define G1_PLANE 10240u
#define G1_STAGE 20480u
#define G1_BOFF  40960u
#define G1_DYN   81920u

__global__ void __launch_bounds__(256, 1)
gemm1_mma(const float* __restrict__ A,    // [32768, 2048]
          const float* __restrict__ Wm,   // [1024, 2048]
          const float* __restrict__ bias) {
    extern __shared__ char dyn[];
    __shared__ float sBias[128];
    const uint32_t uA = smem_u32(dyn);
    const uint32_t uB = uA + G1_BOFF;

    const int tid  = threadIdx.x;
    const int bn   = blockIdx.x * 128;
    const int bm   = blockIdx.y * 128;
    const int warp = tid >> 5, lane = tid & 31;
    const int wm = warp & 3, wn = warp >> 2;

    if (tid < 32)
        *reinterpret_cast<float4*>(&sBias[tid * 4]) =
            *reinterpret_cast<const float4*>(&bias[bn + tid * 4]);

    const int lrow = tid >> 3;   // 0..31
    const int lc4  = tid & 7;

    float4 pa[4], pb[4];
#pragma unroll
    for (int u = 0; u < 4; u++) {
        pa[u] = __ldg(reinterpret_cast<const float4*>(
            &A[(size_t)(bm + lrow + u * 32) * K2H + lc4 * 4]));
        pb[u] = __ldg(reinterpret_cast<const float4*>(
            &Wm[(size_t)(bn + lrow + u * 32) * K2H + lc4 * 4]));
    }

    float acc[2][8][4];
#pragma unroll
    for (int mt = 0; mt < 2; mt++)
#pragma unroll
        for (int nt = 0; nt < 8; nt++)
#pragma unroll
            for (int e = 0; e < 4; e++) acc[mt][nt][e] = 0.f;

    const int g = lane >> 3, gl = lane & 7;
    const uint32_t aRowOff = (uint32_t)((wm * 32 + (g & 1) * 8 + gl) * 80);
    const uint32_t aKOff   = (uint32_t)((g >> 1) * 16);
    const uint32_t bRowOff = (uint32_t)((wn * 64 + (g >> 1) * 8 + gl) * 80);
    const uint32_t bKOff   = (uint32_t)((g & 1) * 16);

    const int PA[6] = {0, 0, 1, 1, 0, 0};
    const int PB[6] = {0, 0, 0, 0, 1, 1};
    const int KO[6] = {0, 32, 0, 32, 0, 32};   // bytes

    // prologue: store stage 0  (8 bytes per float4 per plane!)
#pragma unroll
    for (int u = 0; u < 4; u++) {
        uint32_t off = (uint32_t)((lrow + u * 32) * 80 + lc4 * 8);
        split4_sts(uA + off, uA + G1_PLANE + off, pa[u]);
        split4_sts(uB + off, uB + G1_PLANE + off, pb[u]);
    }
    __syncthreads();

    for (int it = 0; it < 64; it++) {
        const uint32_t so = (uint32_t)(it & 1) * G1_STAGE;
        const uint32_t sn = (uint32_t)((it + 1) & 1) * G1_STAGE;
        if (it < 63) {
            const int kt = (it + 1) * 32;
#pragma unroll
            for (int u = 0; u < 4; u++) {
                pa[u] = __ldg(reinterpret_cast<const float4*>(
                    &A[(size_t)(bm + lrow + u * 32) * K2H + kt + lc4 * 4]));
                pb[u] = __ldg(reinterpret_cast<const float4*>(
                    &Wm[(size_t)(bn + lrow + u * 32) * K2H + kt + lc4 * 4]));
            }
        }
#pragma unroll
        for (int s = 0; s < 6; s++) {
            const uint32_t baseA = uA + so + (uint32_t)PA[s] * G1_PLANE + (uint32_t)KO[s];
            const uint32_t baseB = uB + so + (uint32_t)PB[s] * G1_PLANE + (uint32_t)KO[s];
            uint32_t af[2][4];
#pragma unroll
            for (int mt = 0; mt < 2; mt++)
                ldmx4(af[mt], baseA + aRowOff + (uint32_t)(mt * 1280) + aKOff);
            uint32_t bf[4][4];
#pragma unroll
            for (int p = 0; p < 4; p++)
                ldmx4(bf[p], baseB + bRowOff + (uint32_t)(p * 1280) + bKOff);
#pragma unroll
            for (int mt = 0; mt < 2; mt++)
#pragma unroll
                for (int p = 0; p < 4; p++) {
                    mma_bf16(acc[mt][2 * p + 0], af[mt], bf[p][0], bf[p][1]);
                    mma_bf16(acc[mt][2 * p + 1], af[mt], bf[p][2], bf[p][3]);
                }
        }
        if (it < 63) {
#pragma unroll
            for (int u = 0; u < 4; u++) {
                uint32_t off = (uint32_t)((lrow + u * 32) * 80 + lc4 * 8);
                split4_sts(uA + sn + off, uA + sn + G1_PLANE + off, pa[u]);
                split4_sts(uB + sn + off, uB + sn + G1_PLANE + off, pb[u]);
            }
        }
        __syncthreads();
    }

    // epilogue: add bias, split to bf16 hi/lo planes
    const int mrow0 = bm + wm * 32 + (lane >> 2);
    const int ncol0 = wn * 64 + 2 * (lane & 3);
#pragma unroll
    for (int mt = 0; mt < 2; mt++)
#pragma unroll
        for (int nt = 0; nt < 8; nt++) {
            const int n = ncol0 + nt * 8;
            const float b0 = sBias[n], b1 = sBias[n + 1];
            const size_t r0 = (size_t)(mrow0 + mt * 16) * HH + bn + n;
            const size_t r1 = r0 + (size_t)8 * HH;
            split2_g(&g_red_hi[r0], &g_red_lo[r0],
                     acc[mt][nt][0] + b0, acc[mt][nt][1] + b1);
            split2_g(&g_red_hi[r1], &g_red_lo[r1],
                     acc[mt][nt][2] + b0, acc[mt][nt][3] + b1);
        }
}

// ============================================================
// GEMM2 (HMMA x3): scores[b][s][l] = sum_h red[s][h]*hid[l][h]
// CTA 128(s) x 64(l), K=1024, chunk 32 halves. 8 warps 4m x 2n.
// ============================================================
__global__ void __launch_bounds__(256, 2)
gemm2_mma() {
    __shared__ __nv_bfloat16 s2A[2][128][ROWH];   // [plane][s][k]
    __shared__ __nv_bfloat16 s2B[2][64][ROWH];    // [plane][l][k]

    const int tid = threadIdx.x;
    const int b = blockIdx.y, bs = blockIdx.x * 128;
    const int warp = tid >> 5, lane = tid & 31;
    const int wm = warp & 3, wn = warp >> 2;

    const __nv_bfloat16* Ah = g_red_hi + (size_t)(b * SS + bs) * HH;
    const __nv_bfloat16* Al = g_red_lo + (size_t)(b * SS + bs) * HH;
    const __nv_bfloat16* Bh = g_hid_hi + (size_t)b * HH;
    const __nv_bfloat16* Bl = g_hid_lo + (size_t)b * HH;

    const int ar0 = (tid * 2) >> 2, ac0 = (tid * 2) & 3;
    const int ar1 = (tid * 2 + 1) >> 2, ac1 = (tid * 2 + 1) & 3;
    const int brow = tid >> 2, bc = tid & 3;

    uint4 qa[2][2], qb[2];
    qa[0][0] = *reinterpret_cast<const uint4*>(&Ah[(size_t)ar0 * HH + ac0 * 8]);
    qa[0][1] = *reinterpret_cast<const uint4*>(&Ah[(size_t)ar1 * HH + ac1 * 8]);
    qa[1][0] = *reinterpret_cast<const uint4*>(&Al[(size_t)ar0 * HH + ac0 * 8]);
    qa[1][1] = *reinterpret_cast<const uint4*>(&Al[(size_t)ar1 * HH + ac1 * 8]);
    qb[0] = *reinterpret_cast<const uint4*>(&Bh[(size_t)brow * (BB * HH) + bc * 8]);
    qb[1] = *reinterpret_cast<const uint4*>(&Bl[(size_t)brow * (BB * HH) + bc * 8]);

    float acc[2][4][4];
#pragma unroll
    for (int mt = 0; mt < 2; mt++)
#pragma unroll
        for (int nt = 0; nt < 4; nt++)
#pragma unroll
            for (int e = 0; e < 4; e++) acc[mt][nt][e] = 0.f;

    const int g = lane >> 3, gl = lane & 7;
    const uint32_t uA = smem_u32(s2A), uB = smem_u32(s2B);
    const uint32_t aRowOff = (uint32_t)((wm * 32 + (g & 1) * 8 + gl) * 80);
    const uint32_t aKOff   = (uint32_t)((g >> 1) * 16);
    const uint32_t bRowOff = (uint32_t)((wn * 32 + (g >> 1) * 8 + gl) * 80);
    const uint32_t bKOff   = (uint32_t)((g & 1) * 16);

    const int PA[6] = {0, 0, 1, 1, 0, 0};
    const int PB[6] = {0, 0, 0, 0, 1, 1};
    const int KO[6] = {0, 32, 0, 32, 0, 32};

    for (int it = 0; it < 32; it++) {
        __syncthreads();
        *reinterpret_cast<uint4*>(&s2A[0][ar0][ac0 * 8]) = qa[0][0];
        *reinterpret_cast<uint4*>(&s2A[0][ar1][ac1 * 8]) = qa[0][1];
        *reinterpret_cast<uint4*>(&s2A[1][ar0][ac0 * 8]) = qa[1][0];
        *reinterpret_cast<uint4*>(&s2A[1][ar1][ac1 * 8]) = qa[1][1];
        *reinterpret_cast<uint4*>(&s2B[0][brow][bc * 8]) = qb[0];
        *reinterpret_cast<uint4*>(&s2B[1][brow][bc * 8]) = qb[1];
        __syncthreads();
        if (it < 31) {
            const int ht = (it + 1) * 32;
            qa[0][0] = *reinterpret_cast<const uint4*>(&Ah[(size_t)ar0 * HH + ht + ac0 * 8]);
            qa[0][1] = *reinterpret_cast<const uint4*>(&Ah[(size_t)ar1 * HH + ht + ac1 * 8]);
            qa[1][0] = *reinterpret_cast<const uint4*>(&Al[(size_t)ar0 * HH + ht + ac0 * 8]);
            qa[1][1] = *reinterpret_cast<const uint4*>(&Al[(size_t)ar1 * HH + ht + ac1 * 8]);
            qb[0] = *reinterpret_cast<const uint4*>(&Bh[(size_t)brow * (BB * HH) + ht + bc * 8]);
            qb[1] = *reinterpret_cast<const uint4*>(&Bl[(size_t)brow * (BB * HH) + ht + bc * 8]);
        }
#pragma unroll
        for (int s = 0; s < 6; s++) {
            const uint32_t baseA = uA + (uint32_t)PA[s] * 10240u + (uint32_t)KO[s];
            const uint32_t baseB = uB + (uint32_t)PB[s] * 5120u + (uint32_t)KO[s];
            uint32_t af[2][4];
#pragma unroll
            for (int mt = 0; mt < 2; mt++)
                ldmx4(af[mt], baseA + aRowOff + (uint32_t)(mt * 1280) + aKOff);
            uint32_t bf[2][4];
#pragma unroll
            for (int p = 0; p < 2; p++)
                ldmx4(bf[p], baseB + bRowOff + (uint32_t)(p * 1280) + bKOff);
#pragma unroll
            for (int mt = 0; mt < 2; mt++)
#pragma unroll
                for (int p = 0; p < 2; p++) {
                    mma_bf16(acc[mt][2 * p + 0], af[mt], bf[p][0], bf[p][1]);
                    mma_bf16(acc[mt][2 * p + 1], af[mt], bf[p][2], bf[p][3]);
                }
        }
    }

    const int mrow0 = bs + wm * 32 + (lane >> 2);
    const int ncol0 = wn * 32 + 2 * (lane & 3);
#pragma unroll
    for (int mt = 0; mt < 2; mt++)
#pragma unroll
        for (int nt = 0; nt < 4; nt++) {
            const int n = ncol0 + nt * 8;
            *reinterpret_cast<float2*>(
                &g_scores[((size_t)b * SS + mrow0 + mt * 16) * LL + n]) =
                make_float2(acc[mt][nt][0], acc[mt][nt][1]);
            *reinterpret_cast<float2*>(
                &g_scores[((size_t)b * SS + mrow0 + mt * 16 + 8) * LL + n]) =
                make_float2(acc[mt][nt][2], acc[mt][nt][3]);
        }
}

// ============================================================
// Softmax over s for each (b,l): fp32 weights out + wT bf16 planes
// ============================================================
__global__ void softmax_kernel(float* __restrict__ wout) {
    const int b = blockIdx.x >> 6;
    const int l = blockIdx.x & 63;
    const int tid = threadIdx.x;
    const float* col = g_scores + (size_t)b * SS * LL + l;

    float v[16];
    float m = -3.4e38f;
#pragma unroll
    for (int i = 0; i < 16; i++) {
        v[i] = col[(size_t)(i * 256 + tid) * LL];
        m = fmaxf(m, v[i]);
    }
#pragma unroll
    for (int o = 16; o; o >>= 1) m = fmaxf(m, __shfl_xor_sync(0xffffffffu, m, o));

    __shared__ float red[8];
    __shared__ float bcast;
    if ((tid & 31) == 0) red[tid >> 5] = m;
    __syncthreads();
    if (tid == 0) {
        float mm = red[0];
#pragma unroll
        for (int i = 1; i < 8; i++) mm = fmaxf(mm, red[i]);
        bcast = mm;
    }
    __syncthreads();
    m = bcast;

    float s = 0.f;
#pragma unroll
    for (int i = 0; i < 16; i++) { v[i] = expf(v[i] - m); s += v[i]; }
#pragma unroll
    for (int o = 16; o; o >>= 1) s += __shfl_xor_sync(0xffffffffu, s, o);
    if ((tid & 31) == 0) red[tid >> 5] = s;
    __syncthreads();
    if (tid == 0) {
        float ss = 0.f;
#pragma unroll
        for (int i = 0; i < 8; i++) ss += red[i];
        bcast = ss;
    }
    __syncthreads();
    const float inv = 1.0f / bcast;

    float* out = wout + (size_t)b * SS * LL + l;
    __nv_bfloat16* wth = g_wT_hi + ((size_t)b * LL + l) * SS;
    __nv_bfloat16* wtl = g_wT_lo + ((size_t)b * LL + l) * SS;
#pragma unroll
    for (int i = 0; i < 16; i++) {
        const int si = i * 256 + tid;
        const float w = v[i] * inv;
        out[(size_t)si * LL] = w;
        __nv_bfloat16 h = __float2bfloat16(w);
        wth[si] = h;
        wtl[si] = __float2bfloat16(w - __bfloat162float(h));
    }
}

// ============================================================
// GEMM3 (HMMA x3): ctx[b][l][h] = sum_s wT[b][l][s]*red[s][h]
// CTA 64(l) x 64(h), K=4096, chunk 32. 8 warps 2m x 4n.
// A = wT planes (k-major, non-trans); B = red planes via trans-ldmatrix.
// ============================================================
__global__ void __launch_bounds__(256, 1)
gemm3_mma(float* __restrict__ ctx) {
    __shared__ __nv_bfloat16 sW[2][2][64][ROWH];   // [stg][pl][l][k=s] 20480B
    __shared__ __nv_bfloat16 sR[2][2][32][72];     // [stg][pl][s][h]   18432B

    const int tid = threadIdx.x;
    const int b = blockIdx.y, h0 = blockIdx.x * 64;
    const int warp = tid >> 5, lane = tid & 31;
    const int wm = warp & 1, wn = warp >> 1;

    const __nv_bfloat16* Wh = g_wT_hi + (size_t)b * LL * SS;
    const __nv_bfloat16* Wl = g_wT_lo + (size_t)b * LL * SS;
    const __nv_bfloat16* Rh = g_red_hi + (size_t)b * SS * HH + h0;
    const __nv_bfloat16* Rl = g_red_lo + (size_t)b * SS * HH + h0;

    const int wrow = tid >> 2, wc = tid & 3;   // A staging: 64 rows x 4 f4
    const int srow = tid >> 3, hc = tid & 7;   // B staging: 32 rows x 8 f4

    uint4 qw[2], qr[2];
    qw[0] = *reinterpret_cast<const uint4*>(&Wh[(size_t)wrow * SS + wc * 8]);
    qw[1] = *reinterpret_cast<const uint4*>(&Wl[(size_t)wrow * SS + wc * 8]);
    qr[0] = *reinterpret_cast<const uint4*>(&Rh[(size_t)srow * HH + hc * 8]);
    qr[1] = *reinterpret_cast<const uint4*>(&Rl[(size_t)srow * HH + hc * 8]);

    *reinterpret_cast<uint4*>(&sW[0][0][wrow][wc * 8]) = qw[0];
    *reinterpret_cast<uint4*>(&sW[0][1][wrow][wc * 8]) = qw[1];
    *reinterpret_cast<uint4*>(&sR[0][0][srow][hc * 8]) = qr[0];
    *reinterpret_cast<uint4*>(&sR[0][1][srow][hc * 8]) = qr[1];
    __syncthreads();

    float acc[2][2][4];
#pragma unroll
    for (int mt = 0; mt < 2; mt++)
#pragma unroll
        for (int nt = 0; nt < 2; nt++)
#pragma unroll
            for (int e = 0; e < 4; e++) acc[mt][nt][e] = 0.f;

    const int g = lane >> 3, gl = lane & 7;
    const uint32_t uW = smem_u32(sW), uR = smem_u32(sR);
    const uint32_t aRowOff = (uint32_t)((wm * 32 + (g & 1) * 8 + gl) * 80);
    const uint32_t aKOff   = (uint32_t)((g >> 1) * 16);
    // trans B addressing: lane%16 -> k row (144B stride), lane/16 -> 16B n-chunk
    const uint32_t bOff = (uint32_t)((lane & 15) * 144 + (wn * 16 + (lane >> 4) * 8) * 2);

    const int PA[6]  = {0, 0, 1, 1, 0, 0};
    const int PB[6]  = {0, 0, 0, 0, 1, 1};
    const int KOA[6] = {0, 32, 0, 32, 0, 32};          // A: bytes (16 halves)
    const int KOR[6] = {0, 2304, 0, 2304, 0, 2304};    // B: 16 rows x 144B

    for (int it = 0; it < 128; it++) {
        const uint32_t sow = (uint32_t)(it & 1) * 10240u;
        const uint32_t sor = (uint32_t)(it & 1) * 9216u;
        const uint32_t snw = (uint32_t)((it + 1) & 1) * 10240u;
        const uint32_t snr = (uint32_t)((it + 1) & 1) * 9216u;
        if (it < 127) {
            const int st = (it + 1) * 32;
            qw[0] = *reinterpret_cast<const uint4*>(&Wh[(size_t)wrow * SS + st + wc * 8]);
            qw[1] = *reinterpret_cast<const uint4*>(&Wl[(size_t)wrow * SS + st + wc * 8]);
            qr[0] = *reinterpret_cast<const uint4*>(&Rh[(size_t)(st + srow) * HH + hc * 8]);
            qr[1] = *reinterpret_cast<const uint4*>(&Rl[(size_t)(st + srow) * HH + hc * 8]);
        }
#pragma unroll
        for (int s = 0; s < 6; s++) {
            const uint32_t baseW = uW + sow + (uint32_t)PA[s] * 5120u + (uint32_t)KOA[s];
            const uint32_t baseR = uR + sor + (uint32_t)PB[s] * 4608u + (uint32_t)KOR[s];
            uint32_t af[2][4];
#pragma unroll
            for (int mt = 0; mt < 2; mt++)
                ldmx4(af[mt], baseW + aRowOff + (uint32_t)(mt * 1280) + aKOff);
            uint32_t bfr[4];
            ldmx4t(bfr, baseR + bOff);
#pragma unroll
            for (int mt = 0; mt < 2; mt++) {
                mma_bf16(acc[mt][0], af[mt], bfr[0], bfr[1]);
                mma_bf16(acc[mt][1], af[mt], bfr[2], bfr[3]);
            }
        }
        if (it < 127) {
            *reinterpret_cast<uint4*>(
                reinterpret_cast<char*>(sW) + snw + 0 * 5120u + (size_t)wrow * 80 + wc * 16) = qw[0];
            *reinterpret_cast<uint4*>(
                reinterpret_cast<char*>(sW) + snw + 1 * 5120u + (size_t)wrow * 80 + wc * 16) = qw[1];
            *reinterpret_cast<uint4*>(
                reinterpret_cast<char*>(sR) + snr + 0 * 4608u + (size_t)srow * 144 + hc * 16) = qr[0];
            *reinterpret_cast<uint4*>(
                reinterpret_cast<char*>(sR) + snr + 1 * 4608u + (size_t)srow * 144 + hc * 16) = qr[1];
        }
        __syncthreads();
    }

    // epilogue: direct fp32 ctx write (full K covered per CTA)
#pragma unroll
    for (int mt = 0; mt < 2; mt++)
#pragma unroll
        for (int nt = 0; nt < 2; nt++) {
            const int l = wm * 32 + mt * 16 + (lane >> 2);
            const int h = h0 + wn * 16 + nt * 8 + 2 * (lane & 3);
            *reinterpret_cast<float2*>(&ctx[((size_t)b * LL + l) * HH + h]) =
                make_float2(acc[mt][nt][0], acc[mt][nt][1]);
            *reinterpret_cast<float2*>(&ctx[((size_t)b * LL + l + 8) * HH + h]) =
                make_float2(acc[mt][nt][2], acc[mt][nt][3]);
        }
}

extern "C" void kernel_launch(void* const* d_in, const int* in_sizes, int n_in,
                              void* d_out, int out_size) {
    const float* hidden = (const float*)d_in[0];  // [L, B, H]
    const float* enc    = (const float*)d_in[1];  // [B, S, 2H]
    const float* Wm     = (const float*)d_in[2];  // [H, 2H]
    const float* bias   = (const float*)d_in[3];  // [H]

    float* ctx = (float*)d_out;                   // context [B, L, H]
    float* wts = (float*)d_out + CTX_ELEMS;       // weights [B, S, L]

    cudaFuncSetAttribute(gemm1_mma, cudaFuncAttributeMaxDynamicSharedMemorySize,
                         G1_DYN);
    presplit_hidden<<<512, 256>>>(hidden);
    gemm1_mma<<<dim3(HH / 128, MTOT / 128), 256, G1_DYN>>>(enc, Wm, bias);
    gemm2_mma<<<dim3(SS / 128, BB), 256>>>();
    softmax_kernel<<<BB * LL, 256>>>(wts);
    gemm3_mma<<<dim3(HH / 64, BB), 256>>>(ctx);
}

// round 13
// speedup vs baseline: 1.0036x; 1.0011x over previous
#include <cuda_runtime.h>
#include <cuda_bf16.h>
#include <cstdint>
#include <cstddef>

// Problem dims
#define HH   1024
#define K2H  2048
#define BB   8
#define SS   4096
#define LL   64
#define MTOT (BB * SS)               // 32768
#define CTX_ELEMS (BB * LL * HH)     // 524288

// Scratch (static device memory)
__device__ float g_scores[(size_t)BB * SS * LL];              // 8 MB
__device__ __nv_bfloat16 g_red_hi[(size_t)MTOT * HH];         // 64 MB
__device__ __nv_bfloat16 g_red_lo[(size_t)MTOT * HH];         // 64 MB
__device__ __nv_bfloat16 g_hid_hi[(size_t)LL * BB * HH];      // 1 MB
__device__ __nv_bfloat16 g_hid_lo[(size_t)LL * BB * HH];
__device__ __nv_bfloat16 g_wT_hi[(size_t)BB * LL * SS];       // 4 MB
__device__ __nv_bfloat16 g_wT_lo[(size_t)BB * LL * SS];

__device__ __forceinline__ uint32_t smem_u32(const void* p) {
    uint32_t a;
    asm("{ .reg .u64 t; cvta.to.shared.u64 t, %1; cvt.u32.u64 %0, t; }"
        : "=r"(a) : "l"(p));
    return a;
}
__device__ __forceinline__ uint32_t bf2_bits(__nv_bfloat162 h) {
    union { __nv_bfloat162 b; uint32_t u; } x; x.b = h; return x.u;
}
// ldmatrix x4 (non-transposed, b16)
__device__ __forceinline__ void ldmx4(uint32_t* r, uint32_t addr) {
    asm volatile("ldmatrix.sync.aligned.m8n8.x4.shared.b16 {%0,%1,%2,%3}, [%4];"
                 : "=r"(r[0]), "=r"(r[1]), "=r"(r[2]), "=r"(r[3]) : "r"(addr));
}
// ldmatrix x4 transposed
__device__ __forceinline__ void ldmx4t(uint32_t* r, uint32_t addr) {
    asm volatile("ldmatrix.sync.aligned.m8n8.x4.trans.shared.b16 {%0,%1,%2,%3}, [%4];"
                 : "=r"(r[0]), "=r"(r[1]), "=r"(r[2]), "=r"(r[3]) : "r"(addr));
}
// mma m16n8k16 row.col f32.bf16.bf16.f32, acc in-place
__device__ __forceinline__ void mma_bf16(float* d, const uint32_t* a,
                                         uint32_t b0, uint32_t b1) {
    asm volatile(
        "mma.sync.aligned.m16n8k16.row.col.f32.bf16.bf16.f32 "
        "{%0,%1,%2,%3}, {%4,%5,%6,%7}, {%8,%9}, {%0,%1,%2,%3};"
        : "+f"(d[0]), "+f"(d[1]), "+f"(d[2]), "+f"(d[3])
        : "r"(a[0]), "r"(a[1]), "r"(a[2]), "r"(a[3]), "r"(b0), "r"(b1));
}
// fp32 -> 2-plane bf16 split, store 4 elems (8 bytes/plane) to smem
__device__ __forceinline__ void split4_sts(uint32_t hi_addr, uint32_t lo_addr,
                                           float4 v) {
    __nv_bfloat162 h0 = __floats2bfloat162_rn(v.x, v.y);
    __nv_bfloat162 h1 = __floats2bfloat162_rn(v.z, v.w);
    float2 f0 = __bfloat1622float2(h0);
    float2 f1 = __bfloat1622float2(h1);
    __nv_bfloat162 l0 = __floats2bfloat162_rn(v.x - f0.x, v.y - f0.y);
    __nv_bfloat162 l1 = __floats2bfloat162_rn(v.z - f1.x, v.w - f1.y);
    asm volatile("st.shared.v2.b32 [%0], {%1, %2};"
                 :: "r"(hi_addr), "r"(bf2_bits(h0)), "r"(bf2_bits(h1)) : "memory");
    asm volatile("st.shared.v2.b32 [%0], {%1, %2};"
                 :: "r"(lo_addr), "r"(bf2_bits(l0)), "r"(bf2_bits(l1)) : "memory");
}
// split pair to global planes
__device__ __forceinline__ void split2_g(__nv_bfloat16* hi, __nv_bfloat16* lo,
                                         float a, float b) {
    __nv_bfloat162 h = __floats2bfloat162_rn(a, b);
    float2 f = __bfloat1622float2(h);
    __nv_bfloat162 l = __floats2bfloat162_rn(a - f.x, b - f.y);
    *reinterpret_cast<__nv_bfloat162*>(hi) = h;
    *reinterpret_cast<__nv_bfloat162*>(lo) = l;
}

// ============================================================
// Pre-split hidden [L,B,H] fp32 -> bf16 hi/lo planes
// ============================================================
__global__ void presplit_hidden(const float* __restrict__ hid) {
    int i4 = blockIdx.x * 256 + threadIdx.x;   // 0..131071
    float4 v = __ldg(reinterpret_cast<const float4*>(hid) + i4);
    split2_g(&g_hid_hi[(size_t)i4 * 4], &g_hid_lo[(size_t)i4 * 4], v.x, v.y);
    split2_g(&g_hid_hi[(size_t)i4 * 4 + 2], &g_hid_lo[(size_t)i4 * 4 + 2], v.z, v.w);
}

// ============================================================
// GEMM1 (HMMA split-bf16 x3, double-buffered):
//   reduced = Es @ W^T + bias  -> bf16 hi/lo planes
// CTA 128x128, K-chunk 32 fp32, 8 warps 4m x 2n (32x64 warp tile).
// dyn smem: A[2 stg][2 pl][128][40]h + B same = 80 KB.
// ============================================================
#define ROWH 40
#define G1_PLANE 10240u
#define G1_STAGE 20480u
#define G1_BOFF  40960u
#define G1_DYN   81920u

__global__ void __launch_bounds__(256, 1)
gemm1_mma(const float* __restrict__ A,    // [32768, 2048]
          const float* __restrict__ Wm,   // [1024, 2048]
          const float* __restrict__ bias) {
    extern __shared__ char dyn[];
    __shared__ float sBias[128];
    const uint32_t uA = smem_u32(dyn);
    const uint32_t uB = uA + G1_BOFF;

    const int tid  = threadIdx.x;
    const int bn   = blockIdx.x * 128;
    const int bm   = blockIdx.y * 128;
    const int warp = tid >> 5, lane = tid & 31;
    const int wm = warp & 3, wn = warp >> 2;

    if (tid < 32)
        *reinterpret_cast<float4*>(&sBias[tid * 4]) =
            *reinterpret_cast<const float4*>(&bias[bn + tid * 4]);

    const int lrow = tid >> 3;   // 0..31
    const int lc4  = tid & 7;

    float4 pa[4], pb[4];
#pragma unroll
    for (int u = 0; u < 4; u++) {
        pa[u] = __ldg(reinterpret_cast<const float4*>(
            &A[(size_t)(bm + lrow + u * 32) * K2H + lc4 * 4]));
        pb[u] = __ldg(reinterpret_cast<const float4*>(
            &Wm[(size_t)(bn + lrow + u * 32) * K2H + lc4 * 4]));
    }

    float acc[2][8][4];
#pragma unroll
    for (int mt = 0; mt < 2; mt++)
#pragma unroll
        for (int nt = 0; nt < 8; nt++)
#pragma unroll
            for (int e = 0; e < 4; e++) acc[mt][nt][e] = 0.f;

    const int g = lane >> 3, gl = lane & 7;
    const uint32_t aRowOff = (uint32_t)((wm * 32 + (g & 1) * 8 + gl) * 80);
    const uint32_t aKOff   = (uint32_t)((g >> 1) * 16);
    const uint32_t bRowOff = (uint32_t)((wn * 64 + (g >> 1) * 8 + gl) * 80);
    const uint32_t bKOff   = (uint32_t)((g & 1) * 16);

    const int PA[6] = {0, 0, 1, 1, 0, 0};
    const int PB[6] = {0, 0, 0, 0, 1, 1};
    const int KO[6] = {0, 32, 0, 32, 0, 32};   // bytes

    // prologue: store stage 0  (8 bytes per float4 per plane!)
#pragma unroll
    for (int u = 0; u < 4; u++) {
        uint32_t off = (uint32_t)((lrow + u * 32) * 80 + lc4 * 8);
        split4_sts(uA + off, uA + G1_PLANE + off, pa[u]);
        split4_sts(uB + off, uB + G1_PLANE + off, pb[u]);
    }
    __syncthreads();

    for (int it = 0; it < 64; it++) {
        const uint32_t so = (uint32_t)(it & 1) * G1_STAGE;
        const uint32_t sn = (uint32_t)((it + 1) & 1) * G1_STAGE;
        if (it < 63) {
            const int kt = (it + 1) * 32;
#pragma unroll
            for (int u = 0; u < 4; u++) {
                pa[u] = __ldg(reinterpret_cast<const float4*>(
                    &A[(size_t)(bm + lrow + u * 32) * K2H + kt + lc4 * 4]));
                pb[u] = __ldg(reinterpret_cast<const float4*>(
                    &Wm[(size_t)(bn + lrow + u * 32) * K2H + kt + lc4 * 4]));
            }
        }
#pragma unroll
        for (int s = 0; s < 6; s++) {
            const uint32_t baseA = uA + so + (uint32_t)PA[s] * G1_PLANE + (uint32_t)KO[s];
            const uint32_t baseB = uB + so + (uint32_t)PB[s] * G1_PLANE + (uint32_t)KO[s];
            uint32_t af[2][4];
#pragma unroll
            for (int mt = 0; mt < 2; mt++)
                ldmx4(af[mt], baseA + aRowOff + (uint32_t)(mt * 1280) + aKOff);
            uint32_t bf[4][4];
#pragma unroll
            for (int p = 0; p < 4; p++)
                ldmx4(bf[p], baseB + bRowOff + (uint32_t)(p * 1280) + bKOff);
#pragma unroll
            for (int mt = 0; mt < 2; mt++)
#pragma unroll
                for (int p = 0; p < 4; p++) {
                    mma_bf16(acc[mt][2 * p + 0], af[mt], bf[p][0], bf[p][1]);
                    mma_bf16(acc[mt][2 * p + 1], af[mt], bf[p][2], bf[p][3]);
                }
        }
        if (it < 63) {
#pragma unroll
            for (int u = 0; u < 4; u++) {
                uint32_t off = (uint32_t)((lrow + u * 32) * 80 + lc4 * 8);
                split4_sts(uA + sn + off, uA + sn + G1_PLANE + off, pa[u]);
                split4_sts(uB + sn + off, uB + sn + G1_PLANE + off, pb[u]);
            }
        }
        __syncthreads();
    }

    // epilogue: add bias, split to bf16 hi/lo planes
    const int mrow0 = bm + wm * 32 + (lane >> 2);
    const int ncol0 = wn * 64 + 2 * (lane & 3);
#pragma unroll
    for (int mt = 0; mt < 2; mt++)
#pragma unroll
        for (int nt = 0; nt < 8; nt++) {
            const int n = ncol0 + nt * 8;
            const float b0 = sBias[n], b1 = sBias[n + 1];
            const size_t r0 = (size_t)(mrow0 + mt * 16) * HH + bn + n;
            const size_t r1 = r0 + (size_t)8 * HH;
            split2_g(&g_red_hi[r0], &g_red_lo[r0],
                     acc[mt][nt][0] + b0, acc[mt][nt][1] + b1);
            split2_g(&g_red_hi[r1], &g_red_lo[r1],
                     acc[mt][nt][2] + b0, acc[mt][nt][3] + b1);
        }
}

// ============================================================
// GEMM2 (HMMA x3): scores[b][s][l] = sum_h red[s][h]*hid[l][h]
// CTA 128(s) x 64(l), K=1024, chunk 32 halves. 8 warps 4m x 2n.
// ============================================================
__global__ void __launch_bounds__(256, 2)
gemm2_mma() {
    __shared__ __nv_bfloat16 s2A[2][128][ROWH];   // [plane][s][k]
    __shared__ __nv_bfloat16 s2B[2][64][ROWH];    // [plane][l][k]

    const int tid = threadIdx.x;
    const int b = blockIdx.y, bs = blockIdx.x * 128;
    const int warp = tid >> 5, lane = tid & 31;
    const int wm = warp & 3, wn = warp >> 2;

    const __nv_bfloat16* Ah = g_red_hi + (size_t)(b * SS + bs) * HH;
    const __nv_bfloat16* Al = g_red_lo + (size_t)(b * SS + bs) * HH;
    const __nv_bfloat16* Bh = g_hid_hi + (size_t)b * HH;
    const __nv_bfloat16* Bl = g_hid_lo + (size_t)b * HH;

    const int ar0 = (tid * 2) >> 2, ac0 = (tid * 2) & 3;
    const int ar1 = (tid * 2 + 1) >> 2, ac1 = (tid * 2 + 1) & 3;
    const int brow = tid >> 2, bc = tid & 3;

    uint4 qa[2][2], qb[2];
    qa[0][0] = *reinterpret_cast<const uint4*>(&Ah[(size_t)ar0 * HH + ac0 * 8]);
    qa[0][1] = *reinterpret_cast<const uint4*>(&Ah[(size_t)ar1 * HH + ac1 * 8]);
    qa[1][0] = *reinterpret_cast<const uint4*>(&Al[(size_t)ar0 * HH + ac0 * 8]);
    qa[1][1] = *reinterpret_cast<const uint4*>(&Al[(size_t)ar1 * HH + ac1 * 8]);
    qb[0] = *reinterpret_cast<const uint4*>(&Bh[(size_t)brow * (BB * HH) + bc * 8]);
    qb[1] = *reinterpret_cast<const uint4*>(&Bl[(size_t)brow * (BB * HH) + bc * 8]);

    float acc[2][4][4];
#pragma unroll
    for (int mt = 0; mt < 2; mt++)
#pragma unroll
        for (int nt = 0; nt < 4; nt++)
#pragma unroll
            for (int e = 0; e < 4; e++) acc[mt][nt][e] = 0.f;

    const int g = lane >> 3, gl = lane & 7;
    const uint32_t uA = smem_u32(s2A), uB = smem_u32(s2B);
    const uint32_t aRowOff = (uint32_t)((wm * 32 + (g & 1) * 8 + gl) * 80);
    const uint32_t aKOff   = (uint32_t)((g >> 1) * 16);
    const uint32_t bRowOff = (uint32_t)((wn * 32 + (g >> 1) * 8 + gl) * 80);
    const uint32_t bKOff   = (uint32_t)((g & 1) * 16);

    const int PA[6] = {0, 0, 1, 1, 0, 0};
    const int PB[6] = {0, 0, 0, 0, 1, 1};
    const int KO[6] = {0, 32, 0, 32, 0, 32};

    for (int it = 0; it < 32; it++) {
        __syncthreads();
        *reinterpret_cast<uint4*>(&s2A[0][ar0][ac0 * 8]) = qa[0][0];
        *reinterpret_cast<uint4*>(&s2A[0][ar1][ac1 * 8]) = qa[0][1];
        *reinterpret_cast<uint4*>(&s2A[1][ar0][ac0 * 8]) = qa[1][0];
        *reinterpret_cast<uint4*>(&s2A[1][ar1][ac1 * 8]) = qa[1][1];
        *reinterpret_cast<uint4*>(&s2B[0][brow][bc * 8]) = qb[0];
        *reinterpret_cast<uint4*>(&s2B[1][brow][bc * 8]) = qb[1];
        __syncthreads();
        if (it < 31) {
            const int ht = (it + 1) * 32;
            qa[0][0] = *reinterpret_cast<const uint4*>(&Ah[(size_t)ar0 * HH + ht + ac0 * 8]);
            qa[0][1] = *reinterpret_cast<const uint4*>(&Ah[(size_t)ar1 * HH + ht + ac1 * 8]);
            qa[1][0] = *reinterpret_cast<const uint4*>(&Al[(size_t)ar0 * HH + ht + ac0 * 8]);
            qa[1][1] = *reinterpret_cast<const uint4*>(&Al[(size_t)ar1 * HH + ht + ac1 * 8]);
            qb[0] = *reinterpret_cast<const uint4*>(&Bh[(size_t)brow * (BB * HH) + ht + bc * 8]);
            qb[1] = *reinterpret_cast<const uint4*>(&Bl[(size_t)brow * (BB * HH) + ht + bc * 8]);
        }
#pragma unroll
        for (int s = 0; s < 6; s++) {
            const uint32_t baseA = uA + (uint32_t)PA[s] * 10240u + (uint32_t)KO[s];
            const uint32_t baseB = uB + (uint32_t)PB[s] * 5120u + (uint32_t)KO[s];
            uint32_t af[2][4];
#pragma unroll
            for (int mt = 0; mt < 2; mt++)
                ldmx4(af[mt], baseA + aRowOff + (uint32_t)(mt * 1280) + aKOff);
            uint32_t bf[2][4];
#pragma unroll
            for (int p = 0; p < 2; p++)
                ldmx4(bf[p], baseB + bRowOff + (uint32_t)(p * 1280) + bKOff);
#pragma unroll
            for (int mt = 0; mt < 2; mt++)
#pragma unroll
                for (int p = 0; p < 2; p++) {
                    mma_bf16(acc[mt][2 * p + 0], af[mt], bf[p][0], bf[p][1]);
                    mma_bf16(acc[mt][2 * p + 1], af[mt], bf[p][2], bf[p][3]);
                }
        }
    }

    const int mrow0 = bs + wm * 32 + (lane >> 2);
    const int ncol0 = wn * 32 + 2 * (lane & 3);
#pragma unroll
    for (int mt = 0; mt < 2; mt++)
#pragma unroll
        for (int nt = 0; nt < 4; nt++) {
            const int n = ncol0 + nt * 8;
            *reinterpret_cast<float2*>(
                &g_scores[((size_t)b * SS + mrow0 + mt * 16) * LL + n]) =
                make_float2(acc[mt][nt][0], acc[mt][nt][1]);
            *reinterpret_cast<float2*>(
                &g_scores[((size_t)b * SS + mrow0 + mt * 16 + 8) * LL + n]) =
                make_float2(acc[mt][nt][2], acc[mt][nt][3]);
        }
}

// ============================================================
// Softmax over s for each (b,l): fp32 weights out + wT bf16 planes
// ============================================================
__global__ void softmax_kernel(float* __restrict__ wout) {
    const int b = blockIdx.x >> 6;
    const int l = blockIdx.x & 63;
    const int tid = threadIdx.x;
    const float* col = g_scores + (size_t)b * SS * LL + l;

    float v[16];
    float m = -3.4e38f;
#pragma unroll
    for (int i = 0; i < 16; i++) {
        v[i] = col[(size_t)(i * 256 + tid) * LL];
        m = fmaxf(m, v[i]);
    }
#pragma unroll
    for (int o = 16; o; o >>= 1) m = fmaxf(m, __shfl_xor_sync(0xffffffffu, m, o));

    __shared__ float red[8];
    __shared__ float bcast;
    if ((tid & 31) == 0) red[tid >> 5] = m;
    __syncthreads();
    if (tid == 0) {
        float mm = red[0];
#pragma unroll
        for (int i = 1; i < 8; i++) mm = fmaxf(mm, red[i]);
        bcast = mm;
    }
    __syncthreads();
    m = bcast;

    float s = 0.f;
#pragma unroll
    for (int i = 0; i < 16; i++) { v[i] = expf(v[i] - m); s += v[i]; }
#pragma unroll
    for (int o = 16; o; o >>= 1) s += __shfl_xor_sync(0xffffffffu, s, o);
    if ((tid & 31) == 0) red[tid >> 5] = s;
    __syncthreads();
    if (tid == 0) {
        float ss = 0.f;
#pragma unroll
        for (int i = 0; i < 8; i++) ss += red[i];
        bcast = ss;
    }
    __syncthreads();
    const float inv = 1.0f / bcast;

    float* out = wout + (size_t)b * SS * LL + l;
    __nv_bfloat16* wth = g_wT_hi + ((size_t)b * LL + l) * SS;
    __nv_bfloat16* wtl = g_wT_lo + ((size_t)b * LL + l) * SS;
#pragma unroll
    for (int i = 0; i < 16; i++) {
        const int si = i * 256 + tid;
        const float w = v[i] * inv;
        out[(size_t)si * LL] = w;
        __nv_bfloat16 h = __float2bfloat16(w);
        wth[si] = h;
        wtl[si] = __float2bfloat16(w - __bfloat162float(h));
    }
}

// ============================================================
// GEMM3 (HMMA x3): ctx[b][l][h] = sum_s wT[b][l][s]*red[s][h]
// CTA 64(l) x 64(h), K=4096, chunk 32. 8 warps 2m x 4n.
// A = wT planes (k-major, non-trans); B = red planes via trans-ldmatrix.
// ============================================================
__global__ void __launch_bounds__(256, 1)
gemm3_mma(float* __restrict__ ctx) {
    __shared__ __nv_bfloat16 sW[2][2][64][ROWH];   // [stg][pl][l][k=s] 20480B
    __shared__ __nv_bfloat16 sR[2][2][32][72];     // [stg][pl][s][h]   18432B

    const int tid = threadIdx.x;
    const int b = blockIdx.y, h0 = blockIdx.x * 64;
    const int warp = tid >> 5, lane = tid & 31;
    const int wm = warp & 1, wn = warp >> 1;

    const __nv_bfloat16* Wh = g_wT_hi + (size_t)b * LL * SS;
    const __nv_bfloat16* Wl = g_wT_lo + (size_t)b * LL * SS;
    const __nv_bfloat16* Rh = g_red_hi + (size_t)b * SS * HH + h0;
    const __nv_bfloat16* Rl = g_red_lo + (size_t)b * SS * HH + h0;

    const int wrow = tid >> 2, wc = tid & 3;   // A staging: 64 rows x 4 f4
    const int srow = tid >> 3, hc = tid & 7;   // B staging: 32 rows x 8 f4

    uint4 qw[2], qr[2];
    qw[0] = *reinterpret_cast<const uint4*>(&Wh[(size_t)wrow * SS + wc * 8]);
    qw[1] = *reinterpret_cast<const uint4*>(&Wl[(size_t)wrow * SS + wc * 8]);
    qr[0] = *reinterpret_cast<const uint4*>(&Rh[(size_t)srow * HH + hc * 8]);
    qr[1] = *reinterpret_cast<const uint4*>(&Rl[(size_t)srow * HH + hc * 8]);

    *reinterpret_cast<uint4*>(&sW[0][0][wrow][wc * 8]) = qw[0];
    *reinterpret_cast<uint4*>(&sW[0][1][wrow][wc * 8]) = qw[1];
    *reinterpret_cast<uint4*>(&sR[0][0][srow][hc * 8]) = qr[0];
    *reinterpret_cast<uint4*>(&sR[0][1][srow][hc * 8]) = qr[1];
    __syncthreads();

    float acc[2][2][4];
#pragma unroll
    for (int mt = 0; mt < 2; mt++)
#pragma unroll
        for (int nt = 0; nt < 2; nt++)
#pragma unroll
            for (int e = 0; e < 4; e++) acc[mt][nt][e] = 0.f;

    const int g = lane >> 3, gl = lane & 7;
    const uint32_t uW = smem_u32(sW), uR = smem_u32(sR);
    const uint32_t aRowOff = (uint32_t)((wm * 32 + (g & 1) * 8 + gl) * 80);
    const uint32_t aKOff   = (uint32_t)((g >> 1) * 16);
    // trans B addressing: lane%16 -> k row (144B stride), lane/16 -> 16B n-chunk
    const uint32_t bOff = (uint32_t)((lane & 15) * 144 + (wn * 16 + (lane >> 4) * 8) * 2);

    const int PA[6]  = {0, 0, 1, 1, 0, 0};
    const int PB[6]  = {0, 0, 0, 0, 1, 1};
    const int KOA[6] = {0, 32, 0, 32, 0, 32};          // A: bytes (16 halves)
    const int KOR[6] = {0, 2304, 0, 2304, 0, 2304};    // B: 16 rows x 144B

    for (int it = 0; it < 128; it++) {
        const uint32_t sow = (uint32_t)(it & 1) * 10240u;
        const uint32_t sor = (uint32_t)(it & 1) * 9216u;
        const uint32_t snw = (uint32_t)((it + 1) & 1) * 10240u;
        const uint32_t snr = (uint32_t)((it + 1) & 1) * 9216u;
        if (it < 127) {
            const int st = (it + 1) * 32;
            qw[0] = *reinterpret_cast<const uint4*>(&Wh[(size_t)wrow * SS + st + wc * 8]);
            qw[1] = *reinterpret_cast<const uint4*>(&Wl[(size_t)wrow * SS + st + wc * 8]);
            qr[0] = *reinterpret_cast<const uint4*>(&Rh[(size_t)(st + srow) * HH + hc * 8]);
            qr[1] = *reinterpret_cast<const uint4*>(&Rl[(size_t)(st + srow) * HH + hc * 8]);
        }
#pragma unroll
        for (int s = 0; s < 6; s++) {
            const uint32_t baseW = uW + sow + (uint32_t)PA[s] * 5120u + (uint32_t)KOA[s];
            const uint32_t baseR = uR + sor + (uint32_t)PB[s] * 4608u + (uint32_t)KOR[s];
            uint32_t af[2][4];
#pragma unroll
            for (int mt = 0; mt < 2; mt++)
                ldmx4(af[mt], baseW + aRowOff + (uint32_t)(mt * 1280) + aKOff);
            uint32_t bfr[4];
            ldmx4t(bfr, baseR + bOff);
#pragma unroll
            for (int mt = 0; mt < 2; mt++) {
                mma_bf16(acc[mt][0], af[mt], bfr[0], bfr[1]);
                mma_bf16(acc[mt][1], af[mt], bfr[2], bfr[3]);
            }
        }
        if (it < 127) {
            *reinterpret_cast<uint4*>(
                reinterpret_cast<char*>(sW) + snw + 0 * 5120u + (size_t)wrow * 80 + wc * 16) = qw[0];
            *reinterpret_cast<uint4*>(
                reinterpret_cast<char*>(sW) + snw + 1 * 5120u + (size_t)wrow * 80 + wc * 16) = qw[1];
            *reinterpret_cast<uint4*>(
                reinterpret_cast<char*>(sR) + snr + 0 * 4608u + (size_t)srow * 144 + hc * 16) = qr[0];
            *reinterpret_cast<uint4*>(
                reinterpret_cast<char*>(sR) + snr + 1 * 4608u + (size_t)srow * 144 + hc * 16) = qr[1];
        }
        __syncthreads();
    }

    // epilogue: direct fp32 ctx write (full K covered per CTA)
#pragma unroll
    for (int mt = 0; mt < 2; mt++)
#pragma unroll
        for (int nt = 0; nt < 2; nt++) {
            const int l = wm * 32 + mt * 16 + (lane >> 2);
            const int h = h0 + wn * 16 + nt * 8 + 2 * (lane & 3);
            *reinterpret_cast<float2*>(&ctx[((size_t)b * LL + l) * HH + h]) =
                make_float2(acc[mt][nt][0], acc[mt][nt][1]);
            *reinterpret_cast<float2*>(&ctx[((size_t)b * LL + l + 8) * HH + h]) =
                make_float2(acc[mt][nt][2], acc[mt][nt][3]);
        }
}

extern "C" void kernel_launch(void* const* d_in, const int* in_sizes, int n_in,
                              void* d_out, int out_size) {
    const float* hidden = (const float*)d_in[0];  // [L, B, H]
    const float* enc    = (const float*)d_in[1];  // [B, S, 2H]
    const float* Wm     = (const float*)d_in[2];  // [H, 2H]
    const float* bias   = (const float*)d_in[3];  // [H]

    float* ctx = (float*)d_out;                   // context [B, L, H]
    float* wts = (float*)d_out + CTX_ELEMS;       // weights [B, S, L]

    cudaFuncSetAttribute(gemm1_mma, cudaFuncAttributeMaxDynamicSharedMemorySize,
                         G1_DYN);
    presplit_hidden<<<512, 256>>>(hidden);
    gemm1_mma<<<dim3(HH / 128, MTOT / 128), 256, G1_DYN>>>(enc, Wm, bias);
    gemm2_mma<<<dim3(SS / 128, BB), 256>>>();
    softmax_kernel<<<BB * LL, 256>>>(wts);
    gemm3_mma<<<dim3(HH / 64, BB), 256>>>(ctx);
}